// round 5
// baseline (speedup 1.0000x reference)
#include <cuda_runtime.h>

#define NUM_EMB 1024
#define DIM 256
#define NTOK 65536            // 64 * 32 * 32 tokens
#define TPB 64                // tokens per block
#define KC 32                 // codes per chunk
#define Q_ELEMS (NTOK * DIM)  // 16777216

// ---- scratch (static device globals; no allocation) ----
__device__ float        g_cnorm[NUM_EMB];
__device__ int          g_idx[NTOK];
__device__ unsigned int g_hist[NUM_EMB];
__device__ double       g_sse;

// ============================================================
// K0: init — zero hist/sse, precompute ||c_j||^2
//     sequential scalar mul+add, ascending d (XLA-CPU-reduce style)
// ============================================================
__global__ void k_init(const float* __restrict__ codebook) {
    int i = blockIdx.x * blockDim.x + threadIdx.x;
    if (i < NUM_EMB) {
        const float* row = codebook + i * DIM;
        float s = 0.f;
        for (int d = 0; d < DIM; d++)
            s = __fadd_rn(s, __fmul_rn(row[d], row[d]));
        g_cnorm[i] = s;
        g_hist[i] = 0u;
    }
    if (i == 0) g_sse = 0.0;
}

// ============================================================
// K1: distances + argmin, emulating the reference fp32 arithmetic:
//   d = fl( fl(xx + cc) - 2*dot ),  dot = ascending-k fp32 FMA chain,
//   xx = ascending-d sequential fp32 (mul then add), ties -> lowest idx.
// ============================================================
__global__ void __launch_bounds__(256, 2)
k_argmin(const float* __restrict__ inputs,
         const float* __restrict__ codebook,
         float* __restrict__ out_idx) {
    extern __shared__ float smem[];
    float* xs  = smem;                       // [DIM][TPB] = 16384 floats
    float* cs  = smem + DIM * TPB;           // [KC][DIM]  =  8192 floats
    float* sxx = smem + DIM * TPB + KC * DIM; // [TPB]

    const int tid   = threadIdx.x;
    const int t0    = blockIdx.x * TPB;     // first token of block
    const int batch = t0 >> 10;             // 1024 tokens per batch image
    const int hw0   = t0 & 1023;

    // ---- load x tile (transposed) ----
    {
        int tok = tid & 63;
        int dg  = tid >> 6;   // 0..3
        const float* base = inputs + (size_t)batch * DIM * 1024 + hw0 + tok;
        for (int d = dg; d < DIM; d += 4)
            xs[d * TPB + tok] = base[(size_t)d * 1024];
    }
    __syncthreads();

    // ---- xx per token: strictly sequential scalar fp32, mul then add ----
    if (tid < TPB) {
        float s = 0.f;
        for (int d = 0; d < DIM; d++) {
            float v = xs[d * TPB + tid];
            s = __fadd_rn(s, __fmul_rn(v, v));
        }
        sxx[tid] = s;
    }

    const int lane = tid & 31;   // token group: tokens 2*lane, 2*lane+1
    const int w    = tid >> 5;   // code group: 4 codes per chunk

    float best0 = 3.4e38f, best1 = 3.4e38f;
    int   arg0 = 0, arg1 = 0;

    for (int c0 = 0; c0 < NUM_EMB; c0 += KC) {
        __syncthreads();
        // load code chunk (coalesced float4 copy)
        {
            const float4* src = (const float4*)(codebook + (size_t)c0 * DIM);
            float4* dst = (float4*)cs;
            #pragma unroll
            for (int i = tid; i < KC * DIM / 4; i += 256)
                dst[i] = src[i];
        }
        __syncthreads();

        float acc00 = 0.f, acc01 = 0.f, acc02 = 0.f, acc03 = 0.f;
        float acc10 = 0.f, acc11 = 0.f, acc12 = 0.f, acc13 = 0.f;
        const float* cbase = cs + (w * 4) * DIM;
        const float* xbase = xs + 2 * lane;

        // ascending-k FFMA chains (serial dependence per accumulator
        // guarantees the compiler preserves the order)
        #pragma unroll 4
        for (int d = 0; d < DIM; d++) {
            float2 x2 = *(const float2*)(xbase + d * TPB);
            float c0v = cbase[0 * DIM + d];
            float c1v = cbase[1 * DIM + d];
            float c2v = cbase[2 * DIM + d];
            float c3v = cbase[3 * DIM + d];
            acc00 = __fmaf_rn(x2.x, c0v, acc00);  acc10 = __fmaf_rn(x2.y, c0v, acc10);
            acc01 = __fmaf_rn(x2.x, c1v, acc01);  acc11 = __fmaf_rn(x2.y, c1v, acc11);
            acc02 = __fmaf_rn(x2.x, c2v, acc02);  acc12 = __fmaf_rn(x2.y, c2v, acc12);
            acc03 = __fmaf_rn(x2.x, c3v, acc03);  acc13 = __fmaf_rn(x2.y, c3v, acc13);
        }

        const float xx0 = sxx[2 * lane];
        const float xx1 = sxx[2 * lane + 1];
        int code = c0 + w * 4;
        float a0[4] = {acc00, acc01, acc02, acc03};
        float a1[4] = {acc10, acc11, acc12, acc13};
        #pragma unroll
        for (int j = 0; j < 4; j++) {
            float cn = g_cnorm[code + j];
            // d = fl( fl(xx+cc) - 2*dot )  (2*dot exact, single rounding via fma)
            float d0 = __fmaf_rn(-2.f, a0[j], __fadd_rn(xx0, cn));
            float d1 = __fmaf_rn(-2.f, a1[j], __fadd_rn(xx1, cn));
            if (d0 < best0) { best0 = d0; arg0 = code + j; }  // strict < keeps lowest idx
            if (d1 < best1) { best1 = d1; arg1 = code + j; }
        }
    }

    // ---- reduce across the 8 code-warps per token (lexicographic) ----
    __syncthreads();
    float* rmin = smem;                       // 8 * 128 floats
    int*   rarg = (int*)(smem + 8 * 128);
    rmin[w * 128 + 2 * lane]     = best0;
    rmin[w * 128 + 2 * lane + 1] = best1;
    rarg[w * 128 + 2 * lane]     = arg0;
    rarg[w * 128 + 2 * lane + 1] = arg1;
    __syncthreads();

    if (tid < TPB) {
        float b = rmin[tid];
        int   a = rarg[tid];
        #pragma unroll
        for (int ww = 1; ww < 8; ww++) {
            float v  = rmin[ww * 128 + tid];
            int   va = rarg[ww * 128 + tid];
            if (v < b || (v == b && va < a)) { b = v; a = va; }
        }
        int t = t0 + tid;
        g_idx[t]   = a;
        out_idx[t] = (float)a;
    }
}

// ============================================================
// K2: gather quantized rows, STE write (x + (q - x)), MSE + histogram
// ============================================================
__global__ void __launch_bounds__(256)
k_gather(const float* __restrict__ inputs,
         const float* __restrict__ codebook,
         float* __restrict__ out_q) {
    const int tid   = threadIdx.x;
    const int t0    = blockIdx.x * TPB;
    const int batch = t0 >> 10;
    const int hw0   = t0 & 1023;
    const int tok   = tid & 63;
    const int dg    = tid >> 6;

    const int t   = t0 + tok;
    const int row = g_idx[t];
    const float* crow  = codebook + (size_t)row * DIM;
    const float* xbase = inputs + (size_t)batch * DIM * 1024 + hw0 + tok;
    float*       obase = out_q  + (size_t)batch * DIM * 1024 + hw0 + tok;

    float sse = 0.f;
    #pragma unroll 4
    for (int d = dg; d < DIM; d += 4) {
        float q = crow[d];                 // scattered (codebook L2-resident)
        float x = xbase[(size_t)d * 1024]; // coalesced over tok lanes
        float diff = __fsub_rn(q, x);
        sse = __fmaf_rn(diff, diff, sse);
        // straight-through estimator, reference op order: x + (q - x)
        obase[(size_t)d * 1024] = __fadd_rn(x, diff);
    }

    // block reduce sse -> one double atomic per block
    #pragma unroll
    for (int o = 16; o; o >>= 1) sse += __shfl_down_sync(0xFFFFFFFFu, sse, o);
    __shared__ float warpsum[8];
    if ((tid & 31) == 0) warpsum[tid >> 5] = sse;
    __syncthreads();
    if (tid == 0) {
        float s = 0.f;
        #pragma unroll
        for (int i = 0; i < 8; i++) s += warpsum[i];
        atomicAdd(&g_sse, (double)s);
    }
    if (dg == 0) atomicAdd(&g_hist[row], 1u);   // exactly once per token
}

// ============================================================
// K3: perplexity + loss
// ============================================================
__global__ void k_final(float* __restrict__ out) {
    const int i = threadIdx.x;  // 1024 threads
    float p = (float)g_hist[i] * (1.0f / (float)NTOK);
    float term = p * logf(p + 1e-10f);

    #pragma unroll
    for (int o = 16; o; o >>= 1) term += __shfl_down_sync(0xFFFFFFFFu, term, o);
    __shared__ float ws[32];
    if ((i & 31) == 0) ws[i >> 5] = term;
    __syncthreads();
    if (i < 32) {
        float v = ws[i];
        #pragma unroll
        for (int o = 16; o; o >>= 1) v += __shfl_down_sync(0xFFFFFFFFu, v, o);
        if (i == 0) {
            out[0] = (float)(1.25 * g_sse / (double)Q_ELEMS);  // q_loss + 0.25*e_loss
            out[1 + (size_t)Q_ELEMS] = expf(-v);               // perplexity
        }
    }
}

// ============================================================
// launch
// ============================================================
extern "C" void kernel_launch(void* const* d_in, const int* in_sizes, int n_in,
                              void* d_out, int out_size) {
    const float* inputs   = (const float*)d_in[0];   // [64,256,32,32] f32
    const float* codebook = (const float*)d_in[1];   // [1024,256] f32
    float* out = (float*)d_out;
    // layout: [loss(1), quantized(16777216 NCHW), perplexity(1), idx(65536)]
    float* out_q   = out + 1;
    float* out_idx = out + 2 + (size_t)Q_ELEMS;

    (void)in_sizes; (void)n_in; (void)out_size;

    static const int SMEM_K1 = (DIM * TPB + KC * DIM + TPB) * (int)sizeof(float); // 98560
    cudaFuncSetAttribute(k_argmin, cudaFuncAttributeMaxDynamicSharedMemorySize, SMEM_K1);

    k_init<<<4, 256>>>(codebook);
    k_argmin<<<NTOK / TPB, 256, SMEM_K1>>>(inputs, codebook, out_idx);
    k_gather<<<NTOK / TPB, 256>>>(inputs, codebook, out_q);
    k_final<<<1, 1024>>>(out);
}

// round 6
// speedup vs baseline: 1.1788x; 1.1788x over previous
#include <cuda_runtime.h>

#define NUM_EMB 1024
#define DIM 256
#define NTOK 65536            // 64 * 32 * 32 tokens
#define TPB 64                // tokens per block
#define KC 32                 // codes per chunk
#define Q_ELEMS (NTOK * DIM)  // 16777216

// ---- scratch (static device globals; no allocation) ----
__device__ float        g_cnorm[NUM_EMB];
__device__ int          g_idx[NTOK];
__device__ unsigned int g_hist[NUM_EMB];
__device__ double       g_sse;

// Packed dual-token FMA: each 32-bit lane does fl(x*c + a) — bit-identical
// to the scalar __fmaf_rn chain per token. Serial dependence on acc keeps
// the ascending-d order.
__device__ __forceinline__ void ffma2(unsigned long long& acc,
                                      unsigned long long x2, float c) {
    unsigned long long c2;
    unsigned int ci = __float_as_uint(c);
    asm("mov.b64 %0, {%1, %1};" : "=l"(c2) : "r"(ci));
    asm("fma.rn.f32x2 %0, %1, %2, %0;" : "+l"(acc) : "l"(x2), "l"(c2));
}

// ============================================================
// K0: init — zero hist/sse, precompute ||c_j||^2
//     sequential scalar mul+add, ascending d (matches reference)
// ============================================================
__global__ void k_init(const float* __restrict__ codebook) {
    int i = blockIdx.x * blockDim.x + threadIdx.x;
    if (i < NUM_EMB) {
        const float* row = codebook + i * DIM;
        float s = 0.f;
        for (int d = 0; d < DIM; d++)
            s = __fadd_rn(s, __fmul_rn(row[d], row[d]));
        g_cnorm[i] = s;
        g_hist[i] = 0u;
    }
    if (i == 0) g_sse = 0.0;
}

// ============================================================
// K1: distances + argmin (FFMA2 version)
//   128 threads = 32 token-pair lanes x 4 code-warps (8 codes each).
//   d = fl( fl(xx + cc) - 2*dot ), dot = ascending-d fp32 FMA chain
//   (per packed lane), xx sequential scalar, ties -> lowest idx.
// ============================================================
__global__ void __launch_bounds__(128, 2)
k_argmin(const float* __restrict__ inputs,
         const float* __restrict__ codebook,
         float* __restrict__ out_idx) {
    extern __shared__ float smem[];
    float* xs  = smem;                        // [DIM][TPB] = 16384 floats
    float* cs  = smem + DIM * TPB;            // [KC][DIM]  =  8192 floats
    float* sxx = smem + DIM * TPB + KC * DIM; // [TPB]

    const int tid   = threadIdx.x;            // 0..127
    const int t0    = blockIdx.x * TPB;       // first token of block
    const int batch = t0 >> 10;               // 1024 tokens per batch image
    const int hw0   = t0 & 1023;

    // ---- load x tile (transposed): xs[d][tok] ----
    {
        int tok = tid & 63;
        int dg  = tid >> 6;   // 0..1
        const float* base = inputs + (size_t)batch * DIM * 1024 + hw0 + tok;
        for (int d = dg; d < DIM; d += 2)
            xs[d * TPB + tok] = base[(size_t)d * 1024];
    }
    __syncthreads();

    // ---- xx per token: strictly sequential scalar fp32, mul then add ----
    if (tid < TPB) {
        float s = 0.f;
        for (int d = 0; d < DIM; d++) {
            float v = xs[d * TPB + tid];
            s = __fadd_rn(s, __fmul_rn(v, v));
        }
        sxx[tid] = s;
    }

    const int lane = tid & 31;   // token pair: tokens 2*lane, 2*lane+1
    const int w    = tid >> 5;   // code group: 8 codes per warp per chunk

    float best0 = 3.4e38f, best1 = 3.4e38f;
    int   arg0 = 0, arg1 = 0;

    const float* xbase = xs + 2 * lane;

    for (int c0 = 0; c0 < NUM_EMB; c0 += KC) {
        __syncthreads();
        // load code chunk (coalesced float4 copy)
        {
            const float4* src = (const float4*)(codebook + (size_t)c0 * DIM);
            float4* dst = (float4*)cs;
            #pragma unroll
            for (int i = tid; i < KC * DIM / 4; i += 128)
                dst[i] = src[i];
        }
        __syncthreads();

        const float* cbase = cs + (w * 8) * DIM;

        unsigned long long acc[8];
        #pragma unroll
        for (int j = 0; j < 8; j++) acc[j] = 0ull;

        #pragma unroll 2
        for (int d = 0; d < DIM; d += 4) {
            unsigned long long xa = *(const unsigned long long*)(xbase + (d + 0) * TPB);
            unsigned long long xb = *(const unsigned long long*)(xbase + (d + 1) * TPB);
            unsigned long long xc = *(const unsigned long long*)(xbase + (d + 2) * TPB);
            unsigned long long xd = *(const unsigned long long*)(xbase + (d + 3) * TPB);
            #pragma unroll
            for (int j = 0; j < 8; j++) {
                float4 c4 = *(const float4*)(cbase + j * DIM + d);
                ffma2(acc[j], xa, c4.x);   // ascending d per accumulator:
                ffma2(acc[j], xb, c4.y);   // d, d+1, d+2, d+3
                ffma2(acc[j], xc, c4.z);
                ffma2(acc[j], xd, c4.w);
            }
        }

        const float xx0 = sxx[2 * lane];
        const float xx1 = sxx[2 * lane + 1];
        int code = c0 + w * 8;
        #pragma unroll
        for (int j = 0; j < 8; j++) {
            float a0 = __uint_as_float((unsigned int)(acc[j] & 0xFFFFFFFFull));
            float a1 = __uint_as_float((unsigned int)(acc[j] >> 32));
            float cn = g_cnorm[code + j];
            // d = fl( fl(xx+cc) - 2*dot )  (2*dot exact, single rounding via fma)
            float d0 = __fmaf_rn(-2.f, a0, __fadd_rn(xx0, cn));
            float d1 = __fmaf_rn(-2.f, a1, __fadd_rn(xx1, cn));
            if (d0 < best0) { best0 = d0; arg0 = code + j; }  // strict < keeps lowest idx
            if (d1 < best1) { best1 = d1; arg1 = code + j; }
        }
    }

    // ---- reduce across the 4 code-warps per token (lexicographic) ----
    __syncthreads();
    float* rmin = smem;                       // 4 * 64 floats
    int*   rarg = (int*)(smem + 4 * 64);
    rmin[w * 64 + 2 * lane]     = best0;
    rmin[w * 64 + 2 * lane + 1] = best1;
    rarg[w * 64 + 2 * lane]     = arg0;
    rarg[w * 64 + 2 * lane + 1] = arg1;
    __syncthreads();

    if (tid < TPB) {
        float b = rmin[tid];
        int   a = rarg[tid];
        #pragma unroll
        for (int ww = 1; ww < 4; ww++) {
            float v  = rmin[ww * 64 + tid];
            int   va = rarg[ww * 64 + tid];
            if (v < b || (v == b && va < a)) { b = v; a = va; }
        }
        int t = t0 + tid;
        g_idx[t]   = a;
        out_idx[t] = (float)a;
    }
}

// ============================================================
// K2: gather quantized rows, STE write (x + (q - x)), MSE + histogram
// ============================================================
__global__ void __launch_bounds__(256)
k_gather(const float* __restrict__ inputs,
         const float* __restrict__ codebook,
         float* __restrict__ out_q) {
    const int tid   = threadIdx.x;
    const int t0    = blockIdx.x * TPB;
    const int batch = t0 >> 10;
    const int hw0   = t0 & 1023;
    const int tok   = tid & 63;
    const int dg    = tid >> 6;

    const int t   = t0 + tok;
    const int row = g_idx[t];
    const float* crow  = codebook + (size_t)row * DIM;
    const float* xbase = inputs + (size_t)batch * DIM * 1024 + hw0 + tok;
    float*       obase = out_q  + (size_t)batch * DIM * 1024 + hw0 + tok;

    float sse = 0.f;
    #pragma unroll 4
    for (int d = dg; d < DIM; d += 4) {
        float q = crow[d];                 // scattered (codebook L2-resident)
        float x = xbase[(size_t)d * 1024]; // coalesced over tok lanes
        float diff = __fsub_rn(q, x);
        sse = __fmaf_rn(diff, diff, sse);
        // straight-through estimator, reference op order: x + (q - x)
        obase[(size_t)d * 1024] = __fadd_rn(x, diff);
    }

    // block reduce sse -> one double atomic per block
    #pragma unroll
    for (int o = 16; o; o >>= 1) sse += __shfl_down_sync(0xFFFFFFFFu, sse, o);
    __shared__ float warpsum[8];
    if ((tid & 31) == 0) warpsum[tid >> 5] = sse;
    __syncthreads();
    if (tid == 0) {
        float s = 0.f;
        #pragma unroll
        for (int i = 0; i < 8; i++) s += warpsum[i];
        atomicAdd(&g_sse, (double)s);
    }
    if (dg == 0) atomicAdd(&g_hist[row], 1u);   // exactly once per token
}

// ============================================================
// K3: perplexity + loss
// ============================================================
__global__ void k_final(float* __restrict__ out) {
    const int i = threadIdx.x;  // 1024 threads
    float p = (float)g_hist[i] * (1.0f / (float)NTOK);
    float term = p * logf(p + 1e-10f);

    #pragma unroll
    for (int o = 16; o; o >>= 1) term += __shfl_down_sync(0xFFFFFFFFu, term, o);
    __shared__ float ws[32];
    if ((i & 31) == 0) ws[i >> 5] = term;
    __syncthreads();
    if (i < 32) {
        float v = ws[i];
        #pragma unroll
        for (int o = 16; o; o >>= 1) v += __shfl_down_sync(0xFFFFFFFFu, v, o);
        if (i == 0) {
            out[0] = (float)(1.25 * g_sse / (double)Q_ELEMS);  // q_loss + 0.25*e_loss
            out[1 + (size_t)Q_ELEMS] = expf(-v);               // perplexity
        }
    }
}

// ============================================================
// launch
// ============================================================
extern "C" void kernel_launch(void* const* d_in, const int* in_sizes, int n_in,
                              void* d_out, int out_size) {
    const float* inputs   = (const float*)d_in[0];   // [64,256,32,32] f32
    const float* codebook = (const float*)d_in[1];   // [1024,256] f32
    float* out = (float*)d_out;
    // layout: [loss(1), quantized(16777216 NCHW), perplexity(1), idx(65536)]
    float* out_q   = out + 1;
    float* out_idx = out + 2 + (size_t)Q_ELEMS;

    (void)in_sizes; (void)n_in; (void)out_size;

    static const int SMEM_K1 = (DIM * TPB + KC * DIM + TPB) * (int)sizeof(float); // 98560
    cudaFuncSetAttribute(k_argmin, cudaFuncAttributeMaxDynamicSharedMemorySize, SMEM_K1);

    k_init<<<4, 256>>>(codebook);
    k_argmin<<<NTOK / TPB, 128, SMEM_K1>>>(inputs, codebook, out_idx);
    k_gather<<<NTOK / TPB, 256>>>(inputs, codebook, out_q);
    k_final<<<1, 1024>>>(out);
}